// round 1
// baseline (speedup 1.0000x reference)
#include <cuda_runtime.h>
#include <cstdint>

// Sparse 3D conv: out[m,o] = sum_k sum_i feats[in_idx[k,m], i] * mask[k,m] * kernel[k,i,o]
// Strategy: 64-output-voxel tile per block, register accumulation across all 27
// offsets, packed f32x2 FMA (Blackwell fp32 pipe runs 2-wide via fma.rn.f32x2).

static constexpr int kMVox = 100000;
static constexpr int kKVol = 27;
static constexpr int kCIn  = 32;
static constexpr int kCOut = 64;
static constexpr int M_TILE = 64;

__device__ __forceinline__ void ffma2(unsigned long long& d,
                                      unsigned long long a,
                                      unsigned long long b) {
    asm("fma.rn.f32x2 %0, %1, %2, %0;" : "+l"(d) : "l"(a), "l"(b));
}

__global__ __launch_bounds__(128, 6)
void sparse_conv3d_kernel(const float* __restrict__ feats,
                          const float* __restrict__ kw,
                          const int*   __restrict__ in_idx,
                          const int*   __restrict__ mask,
                          float*       __restrict__ out) {
    // fs: gathered features, transposed [i][m] so m-pairs are contiguous 64-bit
    __shared__ __align__(16) float  fs[kCIn * M_TILE];      // 8 KB
    // ws: weights pre-duplicated as {w,w} so they are ready f32x2 operands
    __shared__ __align__(16) float2 ws[kCIn * kCOut];       // 16 KB
    __shared__ int idx_s[M_TILE];

    const int tid = threadIdx.x;
    const int to  = tid & 15;   // o-group: channels [to*4, to*4+3]
    const int tm  = tid >> 4;   // m-group: rows     [tm*8, tm*8+7]
    const int m0  = blockIdx.x * M_TILE;

    // acc[p][o]: p = m-pair (m = tm*8 + 2p, 2p+1), o = channel within group.
    unsigned long long acc[4][4];
#pragma unroll
    for (int p = 0; p < 4; ++p)
#pragma unroll
        for (int o = 0; o < 4; ++o) acc[p][o] = 0ull;

    for (int k = 0; k < kKVol; ++k) {
        // ---- stage indices (mask folded in as idx = -1) ----
        if (tid < M_TILE) {
            int m = m0 + tid;
            int v = -1;
            if (m < kMVox) {
                int base = k * kMVox + m;
                if (mask[base] != 0) v = in_idx[base];
            }
            idx_s[tid] = v;
        }
        // ---- stage this offset's 32x64 weight slab, duplicated ----
        const float* wk = kw + k * (kCIn * kCOut);
#pragma unroll
        for (int j = 0; j < (kCIn * kCOut) / 128; ++j) {   // 16 iters
            int e = tid + j * 128;
            float w = wk[e];
            ws[e] = make_float2(w, w);
        }
        __syncthreads();

        // ---- gather 64 feature rows into transposed smem tile ----
        {
            int mm = tid & (M_TILE - 1);
            int cb = tid >> 6;                 // 0 or 1: float4 chunk phase
            int ii = idx_s[mm];
            const float4* frow =
                (const float4*)(feats + (long long)(ii < 0 ? 0 : ii) * kCIn);
#pragma unroll
            for (int c = 0; c < 4; ++c) {
                int ch = cb + c * 2;           // chunk 0..7 of the 32-f row
                float4 v = make_float4(0.f, 0.f, 0.f, 0.f);
                if (ii >= 0) v = frow[ch];
                int ib = ch * 4;
                fs[(ib + 0) * M_TILE + mm] = v.x;
                fs[(ib + 1) * M_TILE + mm] = v.y;
                fs[(ib + 2) * M_TILE + mm] = v.z;
                fs[(ib + 3) * M_TILE + mm] = v.w;
            }
        }
        __syncthreads();

        // ---- register-tiled GEMM: [64,32] x [32,64], packed f32x2 ----
#pragma unroll 8
        for (int i = 0; i < kCIn; ++i) {
            const unsigned long long* a2 =
                (const unsigned long long*)(fs + i * M_TILE + tm * 8);
            unsigned long long a0 = a2[0], a1 = a2[1], av2 = a2[2], a3 = a2[3];
            const unsigned long long* w2 =
                (const unsigned long long*)(ws + i * kCOut + to * 4);
            unsigned long long w0 = w2[0], w1 = w2[1], wv2 = w2[2], w3 = w2[3];
            ffma2(acc[0][0], a0, w0);  ffma2(acc[0][1], a0, w1);
            ffma2(acc[0][2], a0, wv2); ffma2(acc[0][3], a0, w3);
            ffma2(acc[1][0], a1, w0);  ffma2(acc[1][1], a1, w1);
            ffma2(acc[1][2], a1, wv2); ffma2(acc[1][3], a1, w3);
            ffma2(acc[2][0], av2, w0); ffma2(acc[2][1], av2, w1);
            ffma2(acc[2][2], av2, wv2);ffma2(acc[2][3], av2, w3);
            ffma2(acc[3][0], a3, w0);  ffma2(acc[3][1], a3, w1);
            ffma2(acc[3][2], a3, wv2); ffma2(acc[3][3], a3, w3);
        }
        __syncthreads();
    }

    // ---- unpack pairs and store: coalesced float4 per output row ----
    float4* out4 = (float4*)out;
#pragma unroll
    for (int p = 0; p < 4; ++p) {
        float2 c0 = *reinterpret_cast<float2*>(&acc[p][0]);
        float2 c1 = *reinterpret_cast<float2*>(&acc[p][1]);
        float2 c2 = *reinterpret_cast<float2*>(&acc[p][2]);
        float2 c3 = *reinterpret_cast<float2*>(&acc[p][3]);
        int m = m0 + tm * 8 + 2 * p;
        if (m < kMVox)
            out4[(long long)m * (kCOut / 4) + to] =
                make_float4(c0.x, c1.x, c2.x, c3.x);
        if (m + 1 < kMVox)
            out4[(long long)(m + 1) * (kCOut / 4) + to] =
                make_float4(c0.y, c1.y, c2.y, c3.y);
    }
}

extern "C" void kernel_launch(void* const* d_in, const int* in_sizes, int n_in,
                              void* d_out, int out_size) {
    const float* feats  = (const float*)d_in[0];
    const float* kernel = (const float*)d_in[1];
    const int*   in_idx = (const int*)d_in[2];
    const int*   maskp  = (const int*)d_in[3];
    float*       out    = (float*)d_out;
    (void)in_sizes; (void)n_in; (void)out_size;

    int grid = (kMVox + M_TILE - 1) / M_TILE;   // 1563
    sparse_conv3d_kernel<<<grid, 128>>>(feats, kernel, in_idx, maskp, out);
}

// round 3
// speedup vs baseline: 3.3200x; 3.3200x over previous
#include <cuda_runtime.h>
#include <cstdint>

// Sparse 3D conv via warp-level bf16 mma.sync (m16n8k16), fp32 emulated with
// a bf16 hi/lo split (3 MMA passes: hi*hi + hi*lo + lo*hi).
// No shared memory, no barriers: A fragments gathered straight from global
// (coalesced within quads), B fragments precomputed in fragment order.

static constexpr int kMVox = 100000;
static constexpr int kKVol = 27;
static constexpr int kCIn  = 32;
static constexpr int kCOut = 64;
static constexpr int M_TILE = 128;     // 8 warps x 16 rows

// B fragments, fragment-order: [koff][nb][lane][8 words]
// words 0..3 = hi {ks0.b0, ks0.b1, ks1.b0, ks1.b1}, words 4..7 = lo same order
__device__ __align__(16) unsigned g_bfrag[kKVol * 8 * 32 * 8];

// split two floats into packed bf16x2 hi and lo (first float in low 16 bits)
__device__ __forceinline__ void split2(float x, float y, unsigned& hi, unsigned& lo) {
    asm("cvt.rn.bf16x2.f32 %0, %1, %2;" : "=r"(hi) : "f"(y), "f"(x));
    float hx = __uint_as_float(hi << 16);
    float hy = __uint_as_float(hi & 0xFFFF0000u);
    float lx = x - hx, ly = y - hy;
    asm("cvt.rn.bf16x2.f32 %0, %1, %2;" : "=r"(lo) : "f"(ly), "f"(lx));
}

__global__ void prep_kernel(const float* __restrict__ kw) {
    int koff = blockIdx.x, tid = threadIdx.x;       // 27 x 256
    int nb = tid >> 5, lane = tid & 31;
    int g = lane >> 2, t = lane & 3;
    int n = nb * 8 + g;
    const float* W = kw + koff * kCIn * kCOut;      // W[i][n]
    unsigned* dst = g_bfrag + ((size_t)(koff * 8 + nb) * 32 + lane) * 8;
#pragma unroll
    for (int s = 0; s < 4; ++s) {                   // s = kstep*2 + bhalf
        int k = 2 * t + 8 * s;
        float vx = W[k * kCOut + n];
        float vy = W[(k + 1) * kCOut + n];
        unsigned h, l;
        split2(vx, vy, h, l);
        dst[s] = h;
        dst[4 + s] = l;
    }
}

__device__ __forceinline__ void mma16816(float* d, const unsigned* a,
                                         unsigned b0, unsigned b1) {
    asm volatile(
        "mma.sync.aligned.m16n8k16.row.col.f32.bf16.bf16.f32 "
        "{%0,%1,%2,%3}, {%4,%5,%6,%7}, {%8,%9}, {%0,%1,%2,%3};"
        : "+f"(d[0]), "+f"(d[1]), "+f"(d[2]), "+f"(d[3])
        : "r"(a[0]), "r"(a[1]), "r"(a[2]), "r"(a[3]), "r"(b0), "r"(b1));
}

__global__ __launch_bounds__(256, 2)
void conv_hmma_kernel(const float* __restrict__ feats,
                      const int*   __restrict__ in_idx,
                      const int*   __restrict__ mask,
                      float*       __restrict__ out) {
    const int w = threadIdx.x >> 5, lane = threadIdx.x & 31;
    const int g = lane >> 2, t = lane & 3;
    const int mbase = blockIdx.x * M_TILE + w * 16;
    const int mA = mbase + g;        // rows for a0/a2 (group row)
    const int mB = mbase + g + 8;    // rows for a1/a3 (group row + 8)

    float acc[8][4];
#pragma unroll
    for (int i = 0; i < 8; ++i)
#pragma unroll
        for (int j = 0; j < 4; ++j) acc[i][j] = 0.f;

    for (int koff = 0; koff < kKVol; ++koff) {
        const size_t off = (size_t)koff * kMVox;
        int i0 = -1, i1 = -1;
        if (mA < kMVox && mask[off + mA]) i0 = in_idx[off + mA];
        if (mB < kMVox && mask[off + mB]) i1 = in_idx[off + mB];

        // gather: thread reads k = 2t+8s .. +1 from its two rows
        float2 r0[4], r1[4];
        const float2* p0 = (const float2*)(feats + (size_t)(i0 < 0 ? 0 : i0) * kCIn);
        const float2* p1 = (const float2*)(feats + (size_t)(i1 < 0 ? 0 : i1) * kCIn);
#pragma unroll
        for (int s = 0; s < 4; ++s) {
            r0[s] = (i0 >= 0) ? p0[t + 4 * s] : make_float2(0.f, 0.f);
            r1[s] = (i1 >= 0) ? p1[t + 4 * s] : make_float2(0.f, 0.f);
        }

        // build A fragments: ah/al[kstep*4 + reg], reg order {a0,a1,a2,a3}
        unsigned ah[8], al[8];
#pragma unroll
        for (int s = 0; s < 4; ++s) {
            unsigned h0, l0, h1, l1;
            split2(r0[s].x, r0[s].y, h0, l0);
            split2(r1[s].x, r1[s].y, h1, l1);
            int base = (s >> 1) * 4 + (s & 1) * 2;
            ah[base] = h0; ah[base + 1] = h1;
            al[base] = l0; al[base + 1] = l1;
        }

#pragma unroll
        for (int nb = 0; nb < 8; ++nb) {
            const uint4* bp = (const uint4*)g_bfrag +
                              ((size_t)(koff * 8 + nb) * 32 + lane) * 2;
            uint4 bh = bp[0], bl = bp[1];
            mma16816(acc[nb], ah + 0, bh.x, bh.y);   // hi*hi ks0
            mma16816(acc[nb], ah + 4, bh.z, bh.w);   // hi*hi ks1
            mma16816(acc[nb], ah + 0, bl.x, bl.y);   // hi*lo ks0
            mma16816(acc[nb], ah + 4, bl.z, bl.w);   // hi*lo ks1
            mma16816(acc[nb], al + 0, bh.x, bh.y);   // lo*hi ks0
            mma16816(acc[nb], al + 4, bh.z, bh.w);   // lo*hi ks1
        }
    }

    // store: d0,d1 -> row mA cols 2t,2t+1 of n-block; d2,d3 -> row mB
#pragma unroll
    for (int nb = 0; nb < 8; ++nb) {
        int n = nb * 8 + 2 * t;
        if (mA < kMVox)
            *(float2*)(out + (size_t)mA * kCOut + n) = make_float2(acc[nb][0], acc[nb][1]);
        if (mB < kMVox)
            *(float2*)(out + (size_t)mB * kCOut + n) = make_float2(acc[nb][2], acc[nb][3]);
    }
}

extern "C" void kernel_launch(void* const* d_in, const int* in_sizes, int n_in,
                              void* d_out, int out_size) {
    const float* feats  = (const float*)d_in[0];
    const float* kernel = (const float*)d_in[1];
    const int*   in_idx = (const int*)d_in[2];
    const int*   maskp  = (const int*)d_in[3];
    float*       out    = (float*)d_out;
    (void)in_sizes; (void)n_in; (void)out_size;

    prep_kernel<<<kKVol, 256>>>(kernel);
    int grid = (kMVox + M_TILE - 1) / M_TILE;   // 782
    conv_hmma_kernel<<<grid, 256>>>(feats, in_idx, maskp, out);
}